// round 2
// baseline (speedup 1.0000x reference)
#include <cuda_runtime.h>
#include <math.h>

// ---------------- problem constants ----------------
#define BSZ 2
#define HH  48
#define WW  48
#define LL  (HH*WW)          // 2304
#define CIN 384              // 2*D_MODEL
#define CC  768              // C_INNER
#define KG  4
#define DD  192              // D_IN
#define NS  16
#define RR  12
#define CDBL 44              // R + 2N
#define BL  (BSZ*LL)         // 4608
#define NCH 16
#define CHL (LL/NCH)         // 144
#define NBKD (BSZ*KG*DD)     // 1536

// ---------------- device scratch ----------------
__device__ float g_xz  [BL*CC];          // in_proj output, [B*L, 768] channel-last
__device__ float g_xc  [BL*CC];          // conv+silu output, channel-last
__device__ float g_xs  [BSZ*KG*DD*LL];   // scan inputs u, [bkd][L]
__device__ float g_xdbl[BSZ*KG*CDBL*LL]; // x_proj out, [bk][c][L]  (c-major!)
__device__ float g_dt  [BSZ*KG*DD*LL];   // softplus(dt), [bkd][L]
__device__ float g_hend [NBKD*NCH*NS];
__device__ float g_aprod[NBKD*NCH*NS];
__device__ float g_hin  [NBKD*NCH*NS];
__device__ float g_ym  [BL*CC];          // y merged spatially, [B*L, 768]
__device__ float g_yln [BL*CC];          // after layernorm

// scan-order index -> spatial index, per direction k
__device__ __forceinline__ int lsp_of(int k, int l) {
    switch (k) {
        case 0:  return l;
        case 1:  return (l % HH) * WW + (l / HH);
        case 2:  return LL - 1 - l;
        default: { int l2 = LL - 1 - l; return (l2 % HH) * WW + (l2 / HH); }
    }
}

__device__ __forceinline__ float softplusf(float x) {
    return (x > 15.f) ? x : log1pf(__expf(x));
}

// ---------------- SGEMM (NT): C[M,N] = A[M,K] * B[N,K]^T ----------------
// 128x128 tile, K-step 16, 256 threads, 8x8 micro-tile (split 4+4 fragments)
#define TBM 128
#define TBN 128
#define TBK 16

__device__ __forceinline__ void sgemm_body(int M, int N, int Kd,
                                           const float* __restrict__ A,
                                           const float* __restrict__ Bw,
                                           float* __restrict__ Co) {
    __shared__ float As[TBK][TBM + 4];
    __shared__ float Bs[TBK][TBN + 4];
    const int tid = threadIdx.x;
    const int bm = blockIdx.y * TBM;
    const int bn = blockIdx.x * TBN;
    const int tx = tid & 15;     // 0..15
    const int ty = tid >> 4;     // 0..15

    float acc[8][8];
#pragma unroll
    for (int i = 0; i < 8; i++)
#pragma unroll
        for (int j = 0; j < 8; j++) acc[i][j] = 0.f;

    for (int k0 = 0; k0 < Kd; k0 += TBK) {
        // load A tile 128x16: 512 float4 / 256 threads = 2 each
#pragma unroll
        for (int it = 0; it < 2; it++) {
            int idx = it * 256 + tid;
            int row = idx >> 2, k4 = (idx & 3) * 4;
            float4 v = *reinterpret_cast<const float4*>(&A[(bm + row) * Kd + k0 + k4]);
            As[k4 + 0][row] = v.x; As[k4 + 1][row] = v.y;
            As[k4 + 2][row] = v.z; As[k4 + 3][row] = v.w;
        }
#pragma unroll
        for (int it = 0; it < 2; it++) {
            int idx = it * 256 + tid;
            int row = idx >> 2, k4 = (idx & 3) * 4;
            float4 v = *reinterpret_cast<const float4*>(&Bw[(bn + row) * Kd + k0 + k4]);
            Bs[k4 + 0][row] = v.x; Bs[k4 + 1][row] = v.y;
            Bs[k4 + 2][row] = v.z; Bs[k4 + 3][row] = v.w;
        }
        __syncthreads();
#pragma unroll
        for (int kk = 0; kk < TBK; kk++) {
            float a[8], b[8];
            float4 a0 = *reinterpret_cast<const float4*>(&As[kk][ty * 4]);
            float4 a1 = *reinterpret_cast<const float4*>(&As[kk][64 + ty * 4]);
            float4 b0 = *reinterpret_cast<const float4*>(&Bs[kk][tx * 4]);
            float4 b1 = *reinterpret_cast<const float4*>(&Bs[kk][64 + tx * 4]);
            a[0]=a0.x; a[1]=a0.y; a[2]=a0.z; a[3]=a0.w;
            a[4]=a1.x; a[5]=a1.y; a[6]=a1.z; a[7]=a1.w;
            b[0]=b0.x; b[1]=b0.y; b[2]=b0.z; b[3]=b0.w;
            b[4]=b1.x; b[5]=b1.y; b[6]=b1.z; b[7]=b1.w;
#pragma unroll
            for (int i = 0; i < 8; i++)
#pragma unroll
                for (int j = 0; j < 8; j++) acc[i][j] = fmaf(a[i], b[j], acc[i][j]);
        }
        __syncthreads();
    }
#pragma unroll
    for (int i = 0; i < 8; i++) {
        int row = bm + ((i < 4) ? (ty * 4 + i) : (64 + ty * 4 + i - 4));
        float4 v0 = make_float4(acc[i][0], acc[i][1], acc[i][2], acc[i][3]);
        float4 v1 = make_float4(acc[i][4], acc[i][5], acc[i][6], acc[i][7]);
        *reinterpret_cast<float4*>(&Co[row * N + bn + tx * 4])      = v0;
        *reinterpret_cast<float4*>(&Co[row * N + bn + 64 + tx * 4]) = v1;
    }
}

__global__ void __launch_bounds__(256) k_gemm_in(const float* __restrict__ A, const float* __restrict__ Bw) {
    sgemm_body(BL, CC, CIN, A, Bw, g_xz);
}
__global__ void __launch_bounds__(256) k_gemm_out(const float* __restrict__ Bw, float* __restrict__ Co) {
    sgemm_body(BL, CIN, CC, g_yln, Bw, Co);
}

// ---------------- depthwise 3x3 conv + SiLU (channel-last) ----------------
__global__ void k_conv_silu(const float* __restrict__ cw, const float* __restrict__ cb) {
    int idx = blockIdx.x * blockDim.x + threadIdx.x;
    if (idx >= BL * CC) return;
    int c   = idx % CC;
    int lsp = (idx / CC) % LL;
    int b   = idx / (CC * LL);
    int h = lsp / WW, w = lsp % WW;
    float acc = cb[c];
#pragma unroll
    for (int dh = 0; dh < 3; dh++) {
        int hh = h + dh - 1;
        if (hh < 0 || hh >= HH) continue;
#pragma unroll
        for (int dw = 0; dw < 3; dw++) {
            int ww = w + dw - 1;
            if (ww < 0 || ww >= WW) continue;
            acc = fmaf(g_xz[(b * LL + hh * WW + ww) * CC + c], cw[c * 9 + dh * 3 + dw], acc);
        }
    }
    float sg = 1.f / (1.f + __expf(-acc));
    g_xc[idx] = acc * sg;
}

// ---------------- gather into scan order: xs[bkd][l] ----------------
__global__ void k_gather(void) {
    __shared__ float t[32][33];
    int bk = blockIdx.z;
    int b = bk / KG, k = bk % KG;
    int l0 = blockIdx.x * 32;
    int d0 = blockIdx.y * 32;
    int tx = threadIdx.x, ty = threadIdx.y;
#pragma unroll
    for (int r = 0; r < 4; r++) {
        int lq = l0 + ty + r * 8;
        int lsp = lsp_of(k, lq);
        t[tx][ty + r * 8] = g_xc[(b * LL + lsp) * CC + k * DD + d0 + tx];
    }
    __syncthreads();
#pragma unroll
    for (int r = 0; r < 4; r++) {
        int dq = ty + r * 8;
        g_xs[(bk * DD + d0 + dq) * LL + l0 + tx] = t[dq][tx];
    }
}

// ---------------- x_proj: xdbl[bk][c][l] = sum_d xpw[k][c][d] * xs[bk][d][l] ----------------
// 512 threads: 4 c-groups (11 channels each) x 128 l
__global__ void __launch_bounds__(512) k_xproj(const float* __restrict__ xpw) {
    __shared__ float ws[CDBL * DD];     // 33 KB
    int bk = blockIdx.y;
    int k = bk % KG;
    for (int i = threadIdx.x; i < CDBL * DD; i += 512)
        ws[i] = xpw[k * CDBL * DD + i];
    __syncthreads();
    int grp = threadIdx.x >> 7;          // 0..3
    int li  = threadIdx.x & 127;
    int l   = blockIdx.x * 128 + li;
    float acc[11];
#pragma unroll
    for (int j = 0; j < 11; j++) acc[j] = 0.f;
    const float* xp = g_xs + bk * DD * LL + l;
    const float* wp = ws + grp * 11 * DD;
#pragma unroll 4
    for (int d = 0; d < DD; d++) {
        float x = xp[d * LL];
#pragma unroll
        for (int j = 0; j < 11; j++) acc[j] = fmaf(wp[j * DD + d], x, acc[j]);
    }
#pragma unroll
    for (int j = 0; j < 11; j++)
        g_xdbl[(bk * CDBL + grp * 11 + j) * LL + l] = acc[j];
}

// ---------------- dt proj + softplus: dt[bkd][l] ----------------
__global__ void __launch_bounds__(128) k_dtproj(const float* __restrict__ dtw, const float* __restrict__ dtb) {
    __shared__ float wd[DD * RR];  // 9 KB
    __shared__ float bd[DD];
    int bk = blockIdx.y;
    int k = bk % KG;
    int l = blockIdx.x * 128 + threadIdx.x;
    for (int i = threadIdx.x; i < DD * RR; i += 128) wd[i] = dtw[k * DD * RR + i];
    for (int i = threadIdx.x; i < DD; i += 128)      bd[i] = dtb[k * DD + i];
    __syncthreads();
    float xr[RR];
#pragma unroll
    for (int r = 0; r < RR; r++)
        xr[r] = g_xdbl[(bk * CDBL + r) * LL + l];
#pragma unroll 2
    for (int dch = 0; dch < DD; dch++) {
        float acc = bd[dch];
#pragma unroll
        for (int r = 0; r < RR; r++) acc = fmaf(xr[r], wd[dch * RR + r], acc);
        g_dt[(bk * DD + dch) * LL + l] = softplusf(acc);
    }
}

// ---------------- scan pass 1: per (bkd, n, chunk) local scan ----------------
__global__ void k_scan1(const float* __restrict__ alog) {
    int gid = blockIdx.x * blockDim.x + threadIdx.x;   // NBKD*NCH*NS threads
    int n = gid & 15;
    int unit = gid >> 4;
    int chunk = unit & (NCH - 1);
    int bkd = unit >> 4;
    int kd = bkd % (KG * DD);
    float An = -__expf(alog[kd * NS + n]);
    const float* dtp = g_dt + bkd * LL + chunk * CHL;
    const float* up  = g_xs + bkd * LL + chunk * CHL;
    int bk = bkd / DD;
    const float* bp = g_xdbl + (bk * CDBL + RR + n) * LL + chunk * CHL;
    float h = 0.f, s = 0.f;
#pragma unroll 4
    for (int i = 0; i < CHL; i++) {
        float d_ = dtp[i];
        float u_ = up[i];
        float b_ = bp[i];
        s += d_;
        h = fmaf(h, __expf(d_ * An), d_ * u_ * b_);
    }
    g_hend[gid]  = h;
    g_aprod[gid] = __expf(An * s);
}

// ---------------- scan pass 2: prefix across chunks ----------------
__global__ void k_scan2(void) {
    int t = blockIdx.x * blockDim.x + threadIdx.x;     // NBKD*NS threads
    int n = t & 15;
    int bkd = t >> 4;
    int base = bkd * (NCH * NS) + n;
    float h = 0.f;
#pragma unroll
    for (int c = 0; c < NCH; c++) {
        g_hin[base + c * NS] = h;
        h = fmaf(g_aprod[base + c * NS], h, g_hend[base + c * NS]);
    }
}

// ---------------- scan pass 3: recompute with prefix, emit y ----------------
__global__ void k_scan3(const float* __restrict__ alog, const float* __restrict__ Ds) {
    int warp_g = blockIdx.x * (blockDim.x / 32) + (threadIdx.x >> 5);
    int lane = threadIdx.x & 31;
    int g = lane >> 4;
    int n = lane & 15;
    int unit = warp_g * 2 + g;          // < NBKD*NCH
    int chunk = unit & (NCH - 1);
    int bkd = unit >> 4;
    int b = bkd / (KG * DD);
    int kd = bkd % (KG * DD);
    int k = kd / DD, dch = kd % DD;
    float An = -__expf(alog[kd * NS + n]);
    float Dv = Ds[kd];
    float h = g_hin[unit * NS + n];
    const float* dtp = g_dt + bkd * LL + chunk * CHL;
    const float* up  = g_xs + bkd * LL + chunk * CHL;
    int bk = bkd / DD;
    const float* bp = g_xdbl + (bk * CDBL + RR + n) * LL + chunk * CHL;
    const float* cp = bp + NS * LL;
    int cglob = k * DD + dch;
#pragma unroll 2
    for (int i = 0; i < CHL; i++) {
        float d_ = dtp[i];
        float u_ = up[i];
        float b_ = bp[i];
        float c_ = cp[i];
        h = fmaf(h, __expf(d_ * An), d_ * u_ * b_);
        float p = h * c_;
        p += __shfl_xor_sync(0xffffffffu, p, 1);
        p += __shfl_xor_sync(0xffffffffu, p, 2);
        p += __shfl_xor_sync(0xffffffffu, p, 4);
        p += __shfl_xor_sync(0xffffffffu, p, 8);
        if (n == 0) {
            int l = chunk * CHL + i;
            int lsp = lsp_of(k, l);
            g_ym[(b * LL + lsp) * CC + cglob] = fmaf(Dv, u_, p);
        }
    }
}

// ---------------- layernorm over C=768 ----------------
__global__ void k_ln(const float* __restrict__ w, const float* __restrict__ bia) {
    int row = blockIdx.x;
    const float* yp = g_ym + row * CC;
    int tid = threadIdx.x;
    float s = 0.f, q = 0.f;
#pragma unroll
    for (int c = tid; c < CC; c += 256) {
        float v = yp[c];
        s += v; q = fmaf(v, v, q);
    }
#pragma unroll
    for (int off = 16; off; off >>= 1) {
        s += __shfl_xor_sync(0xffffffffu, s, off);
        q += __shfl_xor_sync(0xffffffffu, q, off);
    }
    __shared__ float ss[8], qq[8];
    int wid = tid >> 5;
    if ((tid & 31) == 0) { ss[wid] = s; qq[wid] = q; }
    __syncthreads();
    if (tid == 0) {
        float S = 0.f, Q = 0.f;
#pragma unroll
        for (int i = 0; i < 8; i++) { S += ss[i]; Q += qq[i]; }
        float mean = S / (float)CC;
        float var = Q / (float)CC - mean * mean;
        ss[0] = mean;
        qq[0] = rsqrtf(var + 1e-5f);
    }
    __syncthreads();
    float mean = ss[0], rstd = qq[0];
#pragma unroll
    for (int c = tid; c < CC; c += 256) {
        float v = (yp[c] - mean) * rstd;
        g_yln[row * CC + c] = fmaf(v, w[c], bia[c]);
    }
}

// ---------------- host launcher ----------------
extern "C" void kernel_launch(void* const* d_in, const int* in_sizes, int n_in,
                              void* d_out, int out_size) {
    const float* x    = (const float*)d_in[0];
    const float* ipw  = (const float*)d_in[1];
    const float* cw   = (const float*)d_in[2];
    const float* cb   = (const float*)d_in[3];
    const float* xpw  = (const float*)d_in[4];
    const float* dtw  = (const float*)d_in[5];
    const float* dtb  = (const float*)d_in[6];
    const float* alog = (const float*)d_in[7];
    const float* Ds   = (const float*)d_in[8];
    const float* nw   = (const float*)d_in[9];
    const float* nb   = (const float*)d_in[10];
    const float* opw  = (const float*)d_in[11];
    float* out = (float*)d_out;

    // 1. in_proj GEMM: [4608,384] x [768,384]^T -> g_xz
    {
        dim3 grid(CC / TBN, BL / TBM);
        k_gemm_in<<<grid, 256>>>(x, ipw);
    }
    // 2. depthwise conv + SiLU
    {
        int n = BL * CC;
        k_conv_silu<<<(n + 255) / 256, 256>>>(cw, cb);
    }
    // 3. gather to scan order
    {
        dim3 grid(LL / 32, DD / 32, BSZ * KG);
        dim3 blk(32, 8);
        k_gather<<<grid, blk>>>();
    }
    // 4. x_proj
    {
        dim3 grid(LL / 128, BSZ * KG);
        k_xproj<<<grid, 512>>>(xpw);
    }
    // 5. dt proj + softplus
    {
        dim3 grid(LL / 128, BSZ * KG);
        k_dtproj<<<grid, 128>>>(dtw, dtb);
    }
    // 6-8. chunked selective scan
    k_scan1<<<(NBKD * NCH * NS) / 256, 256>>>(alog);
    k_scan2<<<(NBKD * NS) / 256, 256>>>();
    k_scan3<<<(NBKD * NCH) / 2 / 8, 256>>>(alog, Ds);
    // 9. layernorm
    k_ln<<<BL, 256>>>(nw, nb);
    // 10. out_proj GEMM: [4608,768] x [384,768]^T -> out
    {
        dim3 grid(CIN / TBN, BL / TBM);
        k_gemm_out<<<grid, 256>>>(opw, out);
    }
}

// round 3
// speedup vs baseline: 1.0782x; 1.0782x over previous
#include <cuda_runtime.h>
#include <math.h>

// ---------------- problem constants ----------------
#define BSZ 2
#define HH  48
#define WW  48
#define LL  (HH*WW)          // 2304
#define CIN 384              // 2*D_MODEL
#define CC  768              // C_INNER
#define KG  4
#define DD  192              // D_IN
#define NS  16
#define RR  12
#define CDBL 44              // R + 2N
#define BL  (BSZ*LL)         // 4608
#define NCH 16
#define CHL (LL/NCH)         // 144
#define NBKD (BSZ*KG*DD)     // 1536

// ---------------- device scratch ----------------
__device__ float g_xz  [BL*CC];          // in_proj output, [B*L, 768] channel-last
__device__ float g_xc  [BL*CC];          // conv+silu output, channel-last
__device__ float g_xs  [BSZ*KG*DD*LL];   // scan inputs u, [bkd][L]
__device__ float g_xdbl[BSZ*KG*CDBL*LL]; // x_proj out, [bk][c][L]  (c-major)
__device__ float g_dt  [BSZ*KG*DD*LL];   // softplus(dt), [bkd][L]
__device__ float g_hend [NBKD*NCH*NS];
__device__ float g_aprod[NBKD*NCH*NS];
__device__ float g_hin  [NBKD*NCH*NS];
__device__ float g_ym  [BL*CC];          // y merged spatially, [B*L, 768]
__device__ float g_yln [BL*CC];          // after layernorm

// scan-order index -> spatial index, per direction k
__device__ __forceinline__ int lsp_of(int k, int l) {
    switch (k) {
        case 0:  return l;
        case 1:  return (l % HH) * WW + (l / HH);
        case 2:  return LL - 1 - l;
        default: { int l2 = LL - 1 - l; return (l2 % HH) * WW + (l2 / HH); }
    }
}

__device__ __forceinline__ float softplusf(float x) {
    return (x > 15.f) ? x : log1pf(__expf(x));
}

// ---------------- SGEMM (NT): C[M,N] = A[M,K] * B[N,K]^T ----------------
// R1 known-good config: 128x64 tile, 8x4 micro-tile, 256 threads
#define GBM 128
#define GBN 64
#define GBK 16
#define GTM 8
#define GTN 4

__device__ __forceinline__ void sgemm_body(int M, int N, int Kd,
                                           const float* __restrict__ A,
                                           const float* __restrict__ Bw,
                                           float* __restrict__ Co) {
    __shared__ float As[GBK][GBM + 4];
    __shared__ float Bs[GBK][GBN + 4];
    const int tid = threadIdx.x;
    const int bm = blockIdx.y * GBM;
    const int bn = blockIdx.x * GBN;
    const int tx = tid % (GBN / GTN);   // 0..15
    const int ty = tid / (GBN / GTN);   // 0..15

    float acc[GTM][GTN];
#pragma unroll
    for (int i = 0; i < GTM; i++)
#pragma unroll
        for (int j = 0; j < GTN; j++) acc[i][j] = 0.f;

    for (int k0 = 0; k0 < Kd; k0 += GBK) {
#pragma unroll
        for (int it = 0; it < (GBM * GBK) / 256; it++) {
            int idx = it * 256 + tid;
            int m = idx / GBK, kk = idx % GBK;
            As[kk][m] = A[(bm + m) * Kd + k0 + kk];
        }
#pragma unroll
        for (int it = 0; it < (GBN * GBK) / 256; it++) {
            int idx = it * 256 + tid;
            int n = idx / GBK, kk = idx % GBK;
            Bs[kk][n] = Bw[(bn + n) * Kd + k0 + kk];
        }
        __syncthreads();
#pragma unroll
        for (int kk = 0; kk < GBK; kk++) {
            float a[GTM], b[GTN];
            const float4* ap = reinterpret_cast<const float4*>(&As[kk][ty * GTM]);
            float4 a0 = ap[0], a1 = ap[1];
            a[0]=a0.x; a[1]=a0.y; a[2]=a0.z; a[3]=a0.w;
            a[4]=a1.x; a[5]=a1.y; a[6]=a1.z; a[7]=a1.w;
            float4 b0 = *reinterpret_cast<const float4*>(&Bs[kk][tx * GTN]);
            b[0]=b0.x; b[1]=b0.y; b[2]=b0.z; b[3]=b0.w;
#pragma unroll
            for (int i = 0; i < GTM; i++)
#pragma unroll
                for (int j = 0; j < GTN; j++) acc[i][j] = fmaf(a[i], b[j], acc[i][j]);
        }
        __syncthreads();
    }
#pragma unroll
    for (int i = 0; i < GTM; i++) {
        float4 v = make_float4(acc[i][0], acc[i][1], acc[i][2], acc[i][3]);
        *reinterpret_cast<float4*>(&Co[(bm + ty * GTM + i) * N + bn + tx * GTN]) = v;
    }
}

__global__ void k_gemm_in(const float* __restrict__ A, const float* __restrict__ Bw) {
    sgemm_body(BL, CC, CIN, A, Bw, g_xz);
}
__global__ void k_gemm_out(const float* __restrict__ Bw, float* __restrict__ Co) {
    sgemm_body(BL, CIN, CC, g_yln, Bw, Co);
}

// ---------------- depthwise 3x3 conv + SiLU (channel-last) ----------------
__global__ void k_conv_silu(const float* __restrict__ cw, const float* __restrict__ cb) {
    int idx = blockIdx.x * blockDim.x + threadIdx.x;
    if (idx >= BL * CC) return;
    int c   = idx % CC;
    int lsp = (idx / CC) % LL;
    int b   = idx / (CC * LL);
    int h = lsp / WW, w = lsp % WW;
    float acc = cb[c];
#pragma unroll
    for (int dh = 0; dh < 3; dh++) {
        int hh = h + dh - 1;
        if (hh < 0 || hh >= HH) continue;
#pragma unroll
        for (int dw = 0; dw < 3; dw++) {
            int ww = w + dw - 1;
            if (ww < 0 || ww >= WW) continue;
            acc = fmaf(g_xz[(b * LL + hh * WW + ww) * CC + c], cw[c * 9 + dh * 3 + dw], acc);
        }
    }
    float sg = 1.f / (1.f + __expf(-acc));
    g_xc[idx] = acc * sg;
}

// ---------------- gather into scan order: xs[bkd][l] ----------------
__global__ void k_gather(void) {
    __shared__ float t[32][33];
    int bk = blockIdx.z;
    int b = bk / KG, k = bk % KG;
    int l0 = blockIdx.x * 32;
    int d0 = blockIdx.y * 32;
    int tx = threadIdx.x, ty = threadIdx.y;
#pragma unroll
    for (int r = 0; r < 4; r++) {
        int lq = l0 + ty + r * 8;
        int lsp = lsp_of(k, lq);
        t[tx][ty + r * 8] = g_xc[(b * LL + lsp) * CC + k * DD + d0 + tx];
    }
    __syncthreads();
#pragma unroll
    for (int r = 0; r < 4; r++) {
        int dq = ty + r * 8;
        g_xs[(bk * DD + d0 + dq) * LL + l0 + tx] = t[dq][tx];
    }
}

// ---------------- x_proj: xdbl[bk][c][l] = sum_d xpw[k][c][d] * xs[bk][d][l] ----------------
// 256 threads: 4 c-groups (11 channels each) x 64 l; grid (LL/64, B*K) = 288 blocks
__global__ void __launch_bounds__(256) k_xproj(const float* __restrict__ xpw) {
    __shared__ float ws[CDBL * DD];     // 33 KB
    int bk = blockIdx.y;
    int k = bk % KG;
    for (int i = threadIdx.x; i < CDBL * DD; i += 256)
        ws[i] = xpw[k * CDBL * DD + i];
    __syncthreads();
    int grp = threadIdx.x >> 6;          // 0..3
    int li  = threadIdx.x & 63;
    int l   = blockIdx.x * 64 + li;
    float acc[11];
#pragma unroll
    for (int j = 0; j < 11; j++) acc[j] = 0.f;
    const float* xp = g_xs + bk * DD * LL + l;
    const float* wp = ws + grp * 11 * DD;
#pragma unroll 1
    for (int d0 = 0; d0 < DD; d0 += 8) {
        float xv[8];
#pragma unroll
        for (int q = 0; q < 8; q++) xv[q] = xp[(d0 + q) * LL];
#pragma unroll
        for (int q = 0; q < 8; q++) {
#pragma unroll
            for (int j = 0; j < 11; j++)
                acc[j] = fmaf(wp[j * DD + d0 + q], xv[q], acc[j]);
        }
    }
#pragma unroll
    for (int j = 0; j < 11; j++)
        g_xdbl[(bk * CDBL + grp * 11 + j) * LL + l] = acc[j];
}

// ---------------- dt proj + softplus: dt[bkd][l] ----------------
// 256 threads: 4 dch-quarters (48 each) x 64 l; grid (LL/64, B*K) = 288 blocks
__global__ void __launch_bounds__(256) k_dtproj(const float* __restrict__ dtw, const float* __restrict__ dtb) {
    __shared__ float wd[DD * RR];  // 9 KB
    __shared__ float bd[DD];
    int bk = blockIdx.y;
    int k = bk % KG;
    for (int i = threadIdx.x; i < DD * RR; i += 256) wd[i] = dtw[k * DD * RR + i];
    for (int i = threadIdx.x; i < DD; i += 256)      bd[i] = dtb[k * DD + i];
    __syncthreads();
    int quart = threadIdx.x >> 6;        // 0..3
    int li    = threadIdx.x & 63;
    int l     = blockIdx.x * 64 + li;
    float xr[RR];
#pragma unroll
    for (int r = 0; r < RR; r++)
        xr[r] = g_xdbl[(bk * CDBL + r) * LL + l];
    int d0 = quart * 48;
#pragma unroll 4
    for (int dd = 0; dd < 48; dd++) {
        int dch = d0 + dd;
        float acc = bd[dch];
#pragma unroll
        for (int r = 0; r < RR; r++) acc = fmaf(xr[r], wd[dch * RR + r], acc);
        g_dt[(bk * DD + dch) * LL + l] = softplusf(acc);
    }
}

// ---------------- scan pass 1: per (bkd, n, chunk) local scan ----------------
__global__ void __launch_bounds__(128) k_scan1(const float* __restrict__ alog) {
    int gid = blockIdx.x * blockDim.x + threadIdx.x;   // NBKD*NCH*NS threads
    int n = gid & 15;
    int unit = gid >> 4;
    int chunk = unit & (NCH - 1);
    int bkd = unit >> 4;
    int kd = bkd % (KG * DD);
    float An = -__expf(alog[kd * NS + n]);
    const float* dtp = g_dt + bkd * LL + chunk * CHL;
    const float* up  = g_xs + bkd * LL + chunk * CHL;
    int bk = bkd / DD;
    const float* bp = g_xdbl + (bk * CDBL + RR + n) * LL + chunk * CHL;
    float h = 0.f, s = 0.f;
#pragma unroll 4
    for (int i = 0; i < CHL; i++) {
        float d_ = dtp[i];
        float u_ = up[i];
        float b_ = bp[i];
        s += d_;
        h = fmaf(h, __expf(d_ * An), d_ * u_ * b_);
    }
    g_hend[gid]  = h;
    g_aprod[gid] = __expf(An * s);
}

// ---------------- scan pass 2: prefix across chunks ----------------
__global__ void k_scan2(void) {
    int t = blockIdx.x * blockDim.x + threadIdx.x;     // NBKD*NS threads
    int n = t & 15;
    int bkd = t >> 4;
    int base = bkd * (NCH * NS) + n;
    float h = 0.f;
#pragma unroll
    for (int c = 0; c < NCH; c++) {
        g_hin[base + c * NS] = h;
        h = fmaf(g_aprod[base + c * NS], h, g_hend[base + c * NS]);
    }
}

// ---------------- scan pass 3: recompute with prefix, emit y ----------------
__global__ void k_scan3(const float* __restrict__ alog, const float* __restrict__ Ds) {
    int warp_g = blockIdx.x * (blockDim.x / 32) + (threadIdx.x >> 5);
    int lane = threadIdx.x & 31;
    int g = lane >> 4;
    int n = lane & 15;
    int unit = warp_g * 2 + g;          // < NBKD*NCH
    int chunk = unit & (NCH - 1);
    int bkd = unit >> 4;
    int b = bkd / (KG * DD);
    int kd = bkd % (KG * DD);
    int k = kd / DD, dch = kd % DD;
    float An = -__expf(alog[kd * NS + n]);
    float Dv = Ds[kd];
    float h = g_hin[unit * NS + n];
    const float* dtp = g_dt + bkd * LL + chunk * CHL;
    const float* up  = g_xs + bkd * LL + chunk * CHL;
    int bk = bkd / DD;
    const float* bp = g_xdbl + (bk * CDBL + RR + n) * LL + chunk * CHL;
    const float* cp = bp + NS * LL;
    int cglob = k * DD + dch;
#pragma unroll 2
    for (int i = 0; i < CHL; i++) {
        float d_ = dtp[i];
        float u_ = up[i];
        float b_ = bp[i];
        float c_ = cp[i];
        h = fmaf(h, __expf(d_ * An), d_ * u_ * b_);
        float p = h * c_;
        p += __shfl_xor_sync(0xffffffffu, p, 1);
        p += __shfl_xor_sync(0xffffffffu, p, 2);
        p += __shfl_xor_sync(0xffffffffu, p, 4);
        p += __shfl_xor_sync(0xffffffffu, p, 8);
        if (n == 0) {
            int l = chunk * CHL + i;
            int lsp = lsp_of(k, l);
            g_ym[(b * LL + lsp) * CC + cglob] = fmaf(Dv, u_, p);
        }
    }
}

// ---------------- layernorm over C=768 ----------------
__global__ void k_ln(const float* __restrict__ w, const float* __restrict__ bia) {
    int row = blockIdx.x;
    const float* yp = g_ym + row * CC;
    int tid = threadIdx.x;
    float s = 0.f, q = 0.f;
#pragma unroll
    for (int c = tid; c < CC; c += 256) {
        float v = yp[c];
        s += v; q = fmaf(v, v, q);
    }
#pragma unroll
    for (int off = 16; off; off >>= 1) {
        s += __shfl_xor_sync(0xffffffffu, s, off);
        q += __shfl_xor_sync(0xffffffffu, q, off);
    }
    __shared__ float ss[8], qq[8];
    int wid = tid >> 5;
    if ((tid & 31) == 0) { ss[wid] = s; qq[wid] = q; }
    __syncthreads();
    if (tid == 0) {
        float S = 0.f, Q = 0.f;
#pragma unroll
        for (int i = 0; i < 8; i++) { S += ss[i]; Q += qq[i]; }
        float mean = S / (float)CC;
        float var = Q / (float)CC - mean * mean;
        ss[0] = mean;
        qq[0] = rsqrtf(var + 1e-5f);
    }
    __syncthreads();
    float mean = ss[0], rstd = qq[0];
#pragma unroll
    for (int c = tid; c < CC; c += 256) {
        float v = (yp[c] - mean) * rstd;
        g_yln[row * CC + c] = fmaf(v, w[c], bia[c]);
    }
}

// ---------------- host launcher ----------------
extern "C" void kernel_launch(void* const* d_in, const int* in_sizes, int n_in,
                              void* d_out, int out_size) {
    const float* x    = (const float*)d_in[0];
    const float* ipw  = (const float*)d_in[1];
    const float* cw   = (const float*)d_in[2];
    const float* cb   = (const float*)d_in[3];
    const float* xpw  = (const float*)d_in[4];
    const float* dtw  = (const float*)d_in[5];
    const float* dtb  = (const float*)d_in[6];
    const float* alog = (const float*)d_in[7];
    const float* Ds   = (const float*)d_in[8];
    const float* nw   = (const float*)d_in[9];
    const float* nb   = (const float*)d_in[10];
    const float* opw  = (const float*)d_in[11];
    float* out = (float*)d_out;

    // 1. in_proj GEMM: [4608,384] x [768,384]^T -> g_xz
    {
        dim3 grid(CC / GBN, BL / GBM);
        k_gemm_in<<<grid, 256>>>(x, ipw);
    }
    // 2. depthwise conv + SiLU
    {
        int n = BL * CC;
        k_conv_silu<<<(n + 255) / 256, 256>>>(cw, cb);
    }
    // 3. gather to scan order
    {
        dim3 grid(LL / 32, DD / 32, BSZ * KG);
        dim3 blk(32, 8);
        k_gather<<<grid, blk>>>();
    }
    // 4. x_proj
    {
        dim3 grid(LL / 64, BSZ * KG);
        k_xproj<<<grid, 256>>>(xpw);
    }
    // 5. dt proj + softplus
    {
        dim3 grid(LL / 64, BSZ * KG);
        k_dtproj<<<grid, 256>>>(dtw, dtb);
    }
    // 6-8. chunked selective scan
    k_scan1<<<(NBKD * NCH * NS) / 128, 128>>>(alog);
    k_scan2<<<(NBKD * NS) / 256, 256>>>();
    k_scan3<<<(NBKD * NCH) / 2 / 8, 256>>>(alog, Ds);
    // 9. layernorm
    k_ln<<<BL, 256>>>(nw, nb);
    // 10. out_proj GEMM: [4608,768] x [384,768]^T -> out
    {
        dim3 grid(CIN / GBN, BL / GBM);
        k_gemm_out<<<grid, 256>>>(opw, out);
    }
}

// round 4
// speedup vs baseline: 2.0619x; 1.9124x over previous
#include <cuda_runtime.h>
#include <math.h>

// ---------------- problem constants ----------------
#define BSZ 2
#define HH  48
#define WW  48
#define LL  (HH*WW)          // 2304
#define CIN 384              // 2*D_MODEL
#define CC  768              // C_INNER
#define KG  4
#define DD  192              // D_IN
#define NS  16
#define RR  12
#define CDBL 44              // R + 2N
#define BL  (BSZ*LL)         // 4608
#define NCH 16
#define CHL (LL/NCH)         // 144
#define NBKD (BSZ*KG*DD)     // 1536

// ---------------- device scratch ----------------
__device__ float g_xz  [BL*CC];          // in_proj output, [B*L, 768] channel-last
__device__ float g_xc  [BL*CC];          // conv+silu output, channel-last
__device__ float g_xs  [BSZ*KG*DD*LL];   // scan inputs u, [bkd][L]
__device__ float g_dtr [BSZ*KG*RR*LL];   // dt-rank rows, [bk][r][L]
__device__ float g_B   [BSZ*KG*LL*NS];   // B, [bk][l][n]  (n fastest)
__device__ float g_C   [BSZ*KG*LL*NS];   // C, [bk][l][n]
__device__ float g_dt  [BSZ*KG*DD*LL];   // softplus(dt), [bkd][L]
__device__ float g_hend [NBKD*NCH*NS];
__device__ float g_aprod[NBKD*NCH*NS];
__device__ float g_hin  [NBKD*NCH*NS];
__device__ float g_ym  [BL*CC];          // y merged spatially, [B*L, 768]
__device__ float g_yln [BL*CC];          // after layernorm

// scan-order index -> spatial index, per direction k
__device__ __forceinline__ int lsp_of(int k, int l) {
    switch (k) {
        case 0:  return l;
        case 1:  return (l % HH) * WW + (l / HH);
        case 2:  return LL - 1 - l;
        default: { int l2 = LL - 1 - l; return (l2 % HH) * WW + (l2 / HH); }
    }
}

__device__ __forceinline__ float softplusf(float x) {
    return (x > 15.f) ? x : log1pf(__expf(x));
}

// ---------------- SGEMM (NT): C[M,N] = A[M,K] * B[N,K]^T ----------------
// R1 known-good config: 128x64 tile, 8x4 micro-tile, 256 threads
#define GBM 128
#define GBN 64
#define GBK 16
#define GTM 8
#define GTN 4

__device__ __forceinline__ void sgemm_body(int M, int N, int Kd,
                                           const float* __restrict__ A,
                                           const float* __restrict__ Bw,
                                           float* __restrict__ Co) {
    __shared__ float As[GBK][GBM + 4];
    __shared__ float Bs[GBK][GBN + 4];
    const int tid = threadIdx.x;
    const int bm = blockIdx.y * GBM;
    const int bn = blockIdx.x * GBN;
    const int tx = tid % (GBN / GTN);   // 0..15
    const int ty = tid / (GBN / GTN);   // 0..15

    float acc[GTM][GTN];
#pragma unroll
    for (int i = 0; i < GTM; i++)
#pragma unroll
        for (int j = 0; j < GTN; j++) acc[i][j] = 0.f;

    for (int k0 = 0; k0 < Kd; k0 += GBK) {
#pragma unroll
        for (int it = 0; it < (GBM * GBK) / 256; it++) {
            int idx = it * 256 + tid;
            int m = idx / GBK, kk = idx % GBK;
            As[kk][m] = A[(bm + m) * Kd + k0 + kk];
        }
#pragma unroll
        for (int it = 0; it < (GBN * GBK) / 256; it++) {
            int idx = it * 256 + tid;
            int n = idx / GBK, kk = idx % GBK;
            Bs[kk][n] = Bw[(bn + n) * Kd + k0 + kk];
        }
        __syncthreads();
#pragma unroll
        for (int kk = 0; kk < GBK; kk++) {
            float a[GTM], b[GTN];
            const float4* ap = reinterpret_cast<const float4*>(&As[kk][ty * GTM]);
            float4 a0 = ap[0], a1 = ap[1];
            a[0]=a0.x; a[1]=a0.y; a[2]=a0.z; a[3]=a0.w;
            a[4]=a1.x; a[5]=a1.y; a[6]=a1.z; a[7]=a1.w;
            float4 b0 = *reinterpret_cast<const float4*>(&Bs[kk][tx * GTN]);
            b[0]=b0.x; b[1]=b0.y; b[2]=b0.z; b[3]=b0.w;
#pragma unroll
            for (int i = 0; i < GTM; i++)
#pragma unroll
                for (int j = 0; j < GTN; j++) acc[i][j] = fmaf(a[i], b[j], acc[i][j]);
        }
        __syncthreads();
    }
#pragma unroll
    for (int i = 0; i < GTM; i++) {
        float4 v = make_float4(acc[i][0], acc[i][1], acc[i][2], acc[i][3]);
        *reinterpret_cast<float4*>(&Co[(bm + ty * GTM + i) * N + bn + tx * GTN]) = v;
    }
}

__global__ void k_gemm_in(const float* __restrict__ A, const float* __restrict__ Bw) {
    sgemm_body(BL, CC, CIN, A, Bw, g_xz);
}
__global__ void k_gemm_out(const float* __restrict__ Bw, float* __restrict__ Co) {
    sgemm_body(BL, CIN, CC, g_yln, Bw, Co);
}

// ---------------- depthwise 3x3 conv + SiLU (channel-last) ----------------
__global__ void k_conv_silu(const float* __restrict__ cw, const float* __restrict__ cb) {
    int idx = blockIdx.x * blockDim.x + threadIdx.x;
    if (idx >= BL * CC) return;
    int c   = idx % CC;
    int lsp = (idx / CC) % LL;
    int b   = idx / (CC * LL);
    int h = lsp / WW, w = lsp % WW;
    float acc = cb[c];
#pragma unroll
    for (int dh = 0; dh < 3; dh++) {
        int hh = h + dh - 1;
        if (hh < 0 || hh >= HH) continue;
#pragma unroll
        for (int dw = 0; dw < 3; dw++) {
            int ww = w + dw - 1;
            if (ww < 0 || ww >= WW) continue;
            acc = fmaf(g_xz[(b * LL + hh * WW + ww) * CC + c], cw[c * 9 + dh * 3 + dw], acc);
        }
    }
    float sg = 1.f / (1.f + __expf(-acc));
    g_xc[idx] = acc * sg;
}

// ---------------- gather into scan order: xs[bkd][l] ----------------
__global__ void k_gather(void) {
    __shared__ float t[32][33];
    int bk = blockIdx.z;
    int b = bk / KG, k = bk % KG;
    int l0 = blockIdx.x * 32;
    int d0 = blockIdx.y * 32;
    int tx = threadIdx.x, ty = threadIdx.y;
#pragma unroll
    for (int r = 0; r < 4; r++) {
        int lq = l0 + ty + r * 8;
        int lsp = lsp_of(k, lq);
        t[tx][ty + r * 8] = g_xc[(b * LL + lsp) * CC + k * DD + d0 + tx];
    }
    __syncthreads();
#pragma unroll
    for (int r = 0; r < 4; r++) {
        int dq = ty + r * 8;
        g_xs[(bk * DD + d0 + dq) * LL + l0 + tx] = t[dq][tx];
    }
}

// ---------------- x_proj: split outputs into dtr (c-major) + B/C (n-fastest) ---
// 192 threads: grp0 -> dts rows 0..11, grp1 -> B (rows 12..27), grp2 -> C (28..43)
__global__ void __launch_bounds__(192) k_xproj(const float* __restrict__ xpw) {
    __shared__ float ws[CDBL * DD];     // 33 KB
    int bk = blockIdx.y;
    int k = bk % KG;
    for (int i = threadIdx.x; i < CDBL * DD; i += 192)
        ws[i] = xpw[k * CDBL * DD + i];
    __syncthreads();
    int grp = threadIdx.x / 64;          // 0..2
    int li  = threadIdx.x % 64;
    int l   = blockIdx.x * 64 + li;
    const float* xp = g_xs + bk * DD * LL + l;

    if (grp == 0) {
        float acc[RR];
#pragma unroll
        for (int j = 0; j < RR; j++) acc[j] = 0.f;
#pragma unroll 1
        for (int d0 = 0; d0 < DD; d0 += 8) {
            float xv[8];
#pragma unroll
            for (int q = 0; q < 8; q++) xv[q] = xp[(d0 + q) * LL];
#pragma unroll
            for (int q = 0; q < 8; q++)
#pragma unroll
                for (int j = 0; j < RR; j++)
                    acc[j] = fmaf(ws[j * DD + d0 + q], xv[q], acc[j]);
        }
#pragma unroll
        for (int j = 0; j < RR; j++)
            g_dtr[(bk * RR + j) * LL + l] = acc[j];
    } else {
        float acc[NS];
#pragma unroll
        for (int j = 0; j < NS; j++) acc[j] = 0.f;
        const float* wp = ws + (RR + (grp - 1) * NS) * DD;
#pragma unroll 1
        for (int d0 = 0; d0 < DD; d0 += 8) {
            float xv[8];
#pragma unroll
            for (int q = 0; q < 8; q++) xv[q] = xp[(d0 + q) * LL];
#pragma unroll
            for (int q = 0; q < 8; q++)
#pragma unroll
                for (int j = 0; j < NS; j++)
                    acc[j] = fmaf(wp[j * DD + d0 + q], xv[q], acc[j]);
        }
        float* ob = ((grp == 1) ? g_B : g_C) + (bk * LL + l) * NS;
#pragma unroll
        for (int j = 0; j < 4; j++) {
            float4 v = make_float4(acc[j*4], acc[j*4+1], acc[j*4+2], acc[j*4+3]);
            *reinterpret_cast<float4*>(&ob[j * 4]) = v;
        }
    }
}

// ---------------- dt proj + softplus: dt[bkd][l] ----------------
// 256 threads: 4 dch-quarters (48 each) x 64 l; grid (LL/64, B*K) = 288 blocks
__global__ void __launch_bounds__(256) k_dtproj(const float* __restrict__ dtw, const float* __restrict__ dtb) {
    __shared__ float wd[DD * RR];  // 9 KB
    __shared__ float bd[DD];
    int bk = blockIdx.y;
    int k = bk % KG;
    for (int i = threadIdx.x; i < DD * RR; i += 256) wd[i] = dtw[k * DD * RR + i];
    for (int i = threadIdx.x; i < DD; i += 256)      bd[i] = dtb[k * DD + i];
    __syncthreads();
    int quart = threadIdx.x >> 6;        // 0..3
    int li    = threadIdx.x & 63;
    int l     = blockIdx.x * 64 + li;
    float xr[RR];
#pragma unroll
    for (int r = 0; r < RR; r++)
        xr[r] = g_dtr[(bk * RR + r) * LL + l];
    int d0 = quart * 48;
#pragma unroll 4
    for (int dd = 0; dd < 48; dd++) {
        int dch = d0 + dd;
        float acc = bd[dch];
#pragma unroll
        for (int r = 0; r < RR; r++) acc = fmaf(xr[r], wd[dch * RR + r], acc);
        g_dt[(bk * DD + dch) * LL + l] = softplusf(acc);
    }
}

// ---------------- scan pass 1: per (bkd, n, chunk) local scan ----------------
__global__ void __launch_bounds__(128) k_scan1(const float* __restrict__ alog) {
    int gid = blockIdx.x * blockDim.x + threadIdx.x;   // NBKD*NCH*NS threads
    int n = gid & 15;
    int unit = gid >> 4;
    int chunk = unit & (NCH - 1);
    int bkd = unit >> 4;
    int kd = bkd % (KG * DD);
    float An = -__expf(alog[kd * NS + n]);
    const float* dtp = g_dt + bkd * LL + chunk * CHL;
    const float* up  = g_xs + bkd * LL + chunk * CHL;
    int bk = bkd / DD;
    const float* bp = g_B + (bk * LL + chunk * CHL) * NS + n;
    float h = 0.f, s = 0.f;
#pragma unroll 4
    for (int i = 0; i < CHL; i++) {
        float d_ = dtp[i];
        float u_ = up[i];
        float b_ = bp[i * NS];
        s += d_;
        h = fmaf(h, __expf(d_ * An), d_ * u_ * b_);
    }
    g_hend[gid]  = h;
    g_aprod[gid] = __expf(An * s);
}

// ---------------- scan pass 2: prefix across chunks ----------------
__global__ void k_scan2(void) {
    int t = blockIdx.x * blockDim.x + threadIdx.x;     // NBKD*NS threads
    int n = t & 15;
    int bkd = t >> 4;
    int base = bkd * (NCH * NS) + n;
    float h = 0.f;
#pragma unroll
    for (int c = 0; c < NCH; c++) {
        g_hin[base + c * NS] = h;
        h = fmaf(g_aprod[base + c * NS], h, g_hend[base + c * NS]);
    }
}

// ---------------- scan pass 3: recompute with prefix, emit y ----------------
__global__ void k_scan3(const float* __restrict__ alog, const float* __restrict__ Ds) {
    int warp_g = blockIdx.x * (blockDim.x / 32) + (threadIdx.x >> 5);
    int lane = threadIdx.x & 31;
    int g = lane >> 4;
    int n = lane & 15;
    int unit = warp_g * 2 + g;          // < NBKD*NCH
    int chunk = unit & (NCH - 1);
    int bkd = unit >> 4;
    int b = bkd / (KG * DD);
    int kd = bkd % (KG * DD);
    int k = kd / DD, dch = kd % DD;
    float An = -__expf(alog[kd * NS + n]);
    float Dv = Ds[kd];
    float h = g_hin[unit * NS + n];
    const float* dtp = g_dt + bkd * LL + chunk * CHL;
    const float* up  = g_xs + bkd * LL + chunk * CHL;
    int bk = bkd / DD;
    const float* bp = g_B + (bk * LL + chunk * CHL) * NS + n;
    const float* cp = g_C + (bk * LL + chunk * CHL) * NS + n;
    int cglob = k * DD + dch;
#pragma unroll 2
    for (int i = 0; i < CHL; i++) {
        float d_ = dtp[i];
        float u_ = up[i];
        float b_ = bp[i * NS];
        float c_ = cp[i * NS];
        h = fmaf(h, __expf(d_ * An), d_ * u_ * b_);
        float p = h * c_;
        p += __shfl_xor_sync(0xffffffffu, p, 1);
        p += __shfl_xor_sync(0xffffffffu, p, 2);
        p += __shfl_xor_sync(0xffffffffu, p, 4);
        p += __shfl_xor_sync(0xffffffffu, p, 8);
        if (n == 0) {
            int l = chunk * CHL + i;
            int lsp = lsp_of(k, l);
            g_ym[(b * LL + lsp) * CC + cglob] = fmaf(Dv, u_, p);
        }
    }
}

// ---------------- layernorm over C=768 ----------------
__global__ void k_ln(const float* __restrict__ w, const float* __restrict__ bia) {
    int row = blockIdx.x;
    const float* yp = g_ym + row * CC;
    int tid = threadIdx.x;
    float s = 0.f, q = 0.f;
#pragma unroll
    for (int c = tid; c < CC; c += 256) {
        float v = yp[c];
        s += v; q = fmaf(v, v, q);
    }
#pragma unroll
    for (int off = 16; off; off >>= 1) {
        s += __shfl_xor_sync(0xffffffffu, s, off);
        q += __shfl_xor_sync(0xffffffffu, q, off);
    }
    __shared__ float ss[8], qq[8];
    int wid = tid >> 5;
    if ((tid & 31) == 0) { ss[wid] = s; qq[wid] = q; }
    __syncthreads();
    if (tid == 0) {
        float S = 0.f, Q = 0.f;
#pragma unroll
        for (int i = 0; i < 8; i++) { S += ss[i]; Q += qq[i]; }
        float mean = S / (float)CC;
        float var = Q / (float)CC - mean * mean;
        ss[0] = mean;
        qq[0] = rsqrtf(var + 1e-5f);
    }
    __syncthreads();
    float mean = ss[0], rstd = qq[0];
#pragma unroll
    for (int c = tid; c < CC; c += 256) {
        float v = (yp[c] - mean) * rstd;
        g_yln[row * CC + c] = fmaf(v, w[c], bia[c]);
    }
}

// ---------------- host launcher ----------------
extern "C" void kernel_launch(void* const* d_in, const int* in_sizes, int n_in,
                              void* d_out, int out_size) {
    const float* x    = (const float*)d_in[0];
    const float* ipw  = (const float*)d_in[1];
    const float* cw   = (const float*)d_in[2];
    const float* cb   = (const float*)d_in[3];
    const float* xpw  = (const float*)d_in[4];
    const float* dtw  = (const float*)d_in[5];
    const float* dtb  = (const float*)d_in[6];
    const float* alog = (const float*)d_in[7];
    const float* Ds   = (const float*)d_in[8];
    const float* nw   = (const float*)d_in[9];
    const float* nb   = (const float*)d_in[10];
    const float* opw  = (const float*)d_in[11];
    float* out = (float*)d_out;

    // 1. in_proj GEMM: [4608,384] x [768,384]^T -> g_xz
    {
        dim3 grid(CC / GBN, BL / GBM);
        k_gemm_in<<<grid, 256>>>(x, ipw);
    }
    // 2. depthwise conv + SiLU
    {
        int n = BL * CC;
        k_conv_silu<<<(n + 255) / 256, 256>>>(cw, cb);
    }
    // 3. gather to scan order
    {
        dim3 grid(LL / 32, DD / 32, BSZ * KG);
        dim3 blk(32, 8);
        k_gather<<<grid, blk>>>();
    }
    // 4. x_proj
    {
        dim3 grid(LL / 64, BSZ * KG);
        k_xproj<<<grid, 192>>>(xpw);
    }
    // 5. dt proj + softplus
    {
        dim3 grid(LL / 64, BSZ * KG);
        k_dtproj<<<grid, 256>>>(dtw, dtb);
    }
    // 6-8. chunked selective scan
    k_scan1<<<(NBKD * NCH * NS) / 128, 128>>>(alog);
    k_scan2<<<(NBKD * NS) / 256, 256>>>();
    k_scan3<<<(NBKD * NCH) / 2 / 8, 256>>>(alog, Ds);
    // 9. layernorm
    k_ln<<<BL, 256>>>(nw, nb);
    // 10. out_proj GEMM: [4608,768] x [384,768]^T -> out
    {
        dim3 grid(CIN / GBN, BL / GBM);
        k_gemm_out<<<grid, 256>>>(opw, out);
    }
}